// round 1
// baseline (speedup 1.0000x reference)
#include <cuda_runtime.h>
#include <cuda_bf16.h>
#include <cstdint>

// Problem constants
#define NH    96          // heads total
#define NEDGE 1537        // edge table rows (incl. padding row 0)
#define NDIST 5           // MULTI_HOP
#define NP1   129         // N+1
#define NSQ   (129*129)

// Projected edge table: P[d][e][h] = sum_k enc[e,k] * W[d,k,h], bf16.
// 5*1537*96 = 737,760 elems = 1.48 MB device scratch (static, no alloc).
__device__ __align__(16) __nv_bfloat16 g_P[(size_t)NDIST * NEDGE * NH];

__constant__ float c_scale[6] = {0.f, 1.f/3.f, 1.f/6.f, 1.f/9.f, 1.f/12.f, 1.f/15.f};

// ---------------------------------------------------------------------------
// Kernel 1: precompute projected table (tiny GEMM, ~24M MACs)
// grid (1537, 5), block 96: thread h computes P[d][e][h]
// ---------------------------------------------------------------------------
__global__ void proj_kernel(const float* __restrict__ enc,
                            const float* __restrict__ dis) {
    const int e = blockIdx.x;
    const int d = blockIdx.y;
    const int h = threadIdx.x;
    float acc = 0.f;
#pragma unroll
    for (int k = 0; k < 32; ++k) {
        // enc[e,k] uniform across block (L1/L2 broadcast), dis coalesced over h
        acc += enc[e * 32 + k] * dis[(d * 32 + k) * NH + h];
    }
    g_P[((size_t)d * NEDGE + e) * NH + h] = __float2bfloat16(acc);
}

// ---------------------------------------------------------------------------
// Kernel 2: row 0 of the output (virtual token row): trivially small
// out[l,b,a,0,j] = 2*attn_bias[b,0,j] + virt_w[h]
// ---------------------------------------------------------------------------
__global__ void row0_kernel(const float* __restrict__ attn_bias,
                            const float* __restrict__ virt_w,
                            float* __restrict__ out) {
    const int b = blockIdx.x;
    for (int idx = threadIdx.x; idx < NH * NP1; idx += blockDim.x) {
        const int h = idx / NP1;
        const int j = idx - h * NP1;
        const size_t o = ((((size_t)(h >> 3) * 16 + b) * 8) + (h & 7)) * NSQ + j;
        out[o] = 2.f * attn_bias[(size_t)b * NSQ + j] + virt_w[h];
    }
}

// ---------------------------------------------------------------------------
// Kernel 3: main. One CTA per (n, b); 8 warps; warp w owns m = w*16..w*16+15.
// Gather phase: lanes 0..23 each own 4 consecutive h values (h = 4*lane).
//   Per (b,n,m): 15x LDG.64 of bf16x4 from g_P rows (perfectly coalesced 192B
//   row pulls), fp32 accumulate, scale by 1/(3*sp), add spatial bias gather,
//   store to SMEM tile [m][h] (bf16, odd-word row stride -> conflict-free).
// Write phase: warp w owns h = w, w+8, ..., writes contiguous 129-wide output
//   rows out[l,b,a,n+1,:] = 2*attn_bias row + (j==0 ? virt : tile).
// ---------------------------------------------------------------------------
__global__ __launch_bounds__(256) void main_kernel(
    const float* __restrict__ attn_bias,
    const int*   __restrict__ spatial_pos,
    const int*   __restrict__ edge_input,
    const float* __restrict__ spatial_enc,
    const float* __restrict__ virt_w,
    float* __restrict__ out)
{
    // row stride 98 bf16 = 196B: odd 4B-word stride -> conflict-free column reads
    __shared__ __nv_bfloat16 sval[128 * 98];
    __shared__ float s_ab[NP1];
    __shared__ float s_virt[NH];

    const int n    = blockIdx.x;
    const int b    = blockIdx.y;
    const int tid  = threadIdx.x;
    const int warp = tid >> 5;
    const int lane = tid & 31;

    if (tid < NH)  s_virt[tid] = virt_w[tid];
    if (tid < NP1) s_ab[tid] = attn_bias[(size_t)b * NSQ + (size_t)(n + 1) * NP1 + tid];

    // ---- gather phase ----
    if (lane < 24) {
        const int hoff = lane * 4;  // this lane's 4 h-values
#pragma unroll 1
        for (int mi = 0; mi < 16; ++mi) {
            const int m = warp * 16 + mi;
            const int* ip = edge_input + ((size_t)((b * 128 + n) * 128 + m)) * 15;
            float a0 = 0.f, a1 = 0.f, a2 = 0.f, a3 = 0.f;
#pragma unroll
            for (int r = 0; r < 15; ++r) {
                const int e = ip[r];                 // uniform across warp
                const int d = r / 3;                 // compile-time
                const uint2 rv = *reinterpret_cast<const uint2*>(
                    g_P + ((size_t)d * NEDGE + e) * NH + hoff);
                const __nv_bfloat162 v01 = *reinterpret_cast<const __nv_bfloat162*>(&rv.x);
                const __nv_bfloat162 v23 = *reinterpret_cast<const __nv_bfloat162*>(&rv.y);
                const float2 f01 = __bfloat1622float2(v01);
                const float2 f23 = __bfloat1622float2(v23);
                a0 += f01.x; a1 += f01.y; a2 += f23.x; a3 += f23.y;
            }
            const int s = spatial_pos[(size_t)(b * 128 + n) * 128 + m];
            int spn = (s <= 1) ? 1 : (s - 1);
            if (spn > 5) spn = 5;
            const float sc = c_scale[spn];
            const float4 sv = *reinterpret_cast<const float4*>(
                spatial_enc + (size_t)s * NH + hoff);
            a0 = a0 * sc + sv.x;
            a1 = a1 * sc + sv.y;
            a2 = a2 * sc + sv.z;
            a3 = a3 * sc + sv.w;
            // store bf16x4 as two 4B-aligned words (byte offset 196m+8*lane)
            const __nv_bfloat162 o01 = __floats2bfloat162_rn(a0, a1);
            const __nv_bfloat162 o23 = __floats2bfloat162_rn(a2, a3);
            __nv_bfloat162* dst = reinterpret_cast<__nv_bfloat162*>(&sval[m * 98 + hoff]);
            dst[0] = o01;
            dst[1] = o23;
        }
    }
    __syncthreads();

    // ---- write phase: warp w handles h = w + 8*k ----
#pragma unroll 1
    for (int hk = 0; hk < 12; ++hk) {
        const int h = warp + 8 * hk;
        const float vw = s_virt[h];
        const size_t obase = ((((size_t)(h >> 3) * 16 + b) * 8) + (h & 7)) * NSQ
                             + (size_t)(n + 1) * NP1;
#pragma unroll
        for (int jj = 0; jj < 4; ++jj) {
            const int j = lane + 32 * jj;
            const float v = (j == 0) ? vw : __bfloat162float(sval[(j - 1) * 98 + h]);
            out[obase + j] = 2.f * s_ab[j] + v;
        }
        if (lane == 0)
            out[obase + 128] = 2.f * s_ab[128] + __bfloat162float(sval[127 * 98 + h]);
    }
}

// ---------------------------------------------------------------------------
// Launch. Input order (metadata): attn_bias f32, spatial_pos i32, node_attr f32
// (unused), edge_input i32, edge_enc_w f32, edge_dis_w f32, spatial_enc_w f32,
// virt_w f32. Output f32 [12,16,8,129,129].
// ---------------------------------------------------------------------------
extern "C" void kernel_launch(void* const* d_in, const int* in_sizes, int n_in,
                              void* d_out, int out_size) {
    const float* attn_bias     = (const float*)d_in[0];
    const int*   spatial_pos   = (const int*)  d_in[1];
    const int*   edge_input    = (const int*)  d_in[3];
    const float* edge_enc_w    = (const float*)d_in[4];
    const float* edge_dis_w    = (const float*)d_in[5];
    const float* spatial_enc_w = (const float*)d_in[6];
    const float* virt_w        = (const float*)d_in[7];
    float* out = (float*)d_out;

    proj_kernel<<<dim3(NEDGE, NDIST), NH>>>(edge_enc_w, edge_dis_w);
    row0_kernel<<<16, 256>>>(attn_bias, virt_w, out);
    main_kernel<<<dim3(128, 16), 256>>>(attn_bias, spatial_pos, edge_input,
                                        spatial_enc_w, virt_w, out);
}

// round 2
// speedup vs baseline: 1.1430x; 1.1430x over previous
#include <cuda_runtime.h>
#include <cuda_bf16.h>
#include <cuda_fp8.h>
#include <cstdint>

// Problem constants
#define NH    96          // heads total
#define NEDGE 1537        // edge table rows (incl. padding row 0)
#define NDIST 5           // MULTI_HOP
#define NP1   129         // N+1
#define NSQ   (129*129)

#define P_SCALE 4096.0f   // fp8 table pre-scale

// Projected edge table, fp8 e4m3, scaled by P_SCALE:
// P8[d][e][h] = fp8(P_SCALE * sum_k enc[e,k] * W[d,k,h]).
// 5*1537*96 = 737,760 bytes. Row = 96B = exactly 3 L2 sectors.
__device__ __align__(16) unsigned char g_P8[(size_t)NDIST * NEDGE * NH];
// Spatial bias table converted to bf16: 512*96 entries.
__device__ __align__(16) __nv_bfloat16 g_SP[512 * NH];

// hop normalizer with the fp8 scale folded in: 1/(3*sp*P_SCALE)
__constant__ float c_scale[6] = {0.f,
    1.f/(3.f*P_SCALE), 1.f/(6.f*P_SCALE), 1.f/(9.f*P_SCALE),
    1.f/(12.f*P_SCALE), 1.f/(15.f*P_SCALE)};

// ---------------------------------------------------------------------------
// Kernel 1: precompute projected table (24M MACs).
// grid (ceil(1537/16), 5), block 96. dis column cached in 32 regs,
// 16 enc rows staged through SMEM.
// ---------------------------------------------------------------------------
__global__ void proj_kernel(const float* __restrict__ enc,
                            const float* __restrict__ dis) {
    __shared__ float s_enc[16 * 32];
    const int d  = blockIdx.y;
    const int h  = threadIdx.x;          // 0..95
    const int e0 = blockIdx.x * 16;

    float w[32];
#pragma unroll
    for (int k = 0; k < 32; ++k)
        w[k] = dis[(d * 32 + k) * NH + h];   // coalesced over h

    for (int i = h; i < 16 * 32; i += 96) {
        const int e = e0 + (i >> 5);
        s_enc[i] = (e < NEDGE) ? enc[e * 32 + (i & 31)] : 0.f;
    }
    __syncthreads();

#pragma unroll 4
    for (int ei = 0; ei < 16; ++ei) {
        const int e = e0 + ei;
        if (e >= NEDGE) break;
        float acc = 0.f;
#pragma unroll
        for (int k = 0; k < 32; ++k)
            acc += s_enc[ei * 32 + k] * w[k];
        g_P8[((size_t)d * NEDGE + e) * NH + h] =
            __nv_cvt_float_to_fp8(acc * P_SCALE, __NV_SATFINITE, __NV_E4M3);
    }
}

// ---------------------------------------------------------------------------
// Kernel 2: convert spatial_enc to bf16 table.
// ---------------------------------------------------------------------------
__global__ void cvt_spatial_kernel(const float* __restrict__ sp) {
    const int i = blockIdx.x * 256 + threadIdx.x;
    if (i < 512 * NH) g_SP[i] = __float2bfloat16(sp[i]);
}

// ---------------------------------------------------------------------------
// Kernel 3: row 0 of the output (virtual token row).
// out[l,b,a,0,j] = 2*attn_bias[b,0,j] + virt_w[h]
// ---------------------------------------------------------------------------
__global__ void row0_kernel(const float* __restrict__ attn_bias,
                            const float* __restrict__ virt_w,
                            float* __restrict__ out) {
    const int b = blockIdx.x;
    for (int idx = threadIdx.x; idx < NH * NP1; idx += blockDim.x) {
        const int h = idx / NP1;
        const int j = idx - h * NP1;
        const size_t o = ((((size_t)(h >> 3) * 16 + b) * 8) + (h & 7)) * NSQ + j;
        out[o] = 2.f * attn_bias[(size_t)b * NSQ + j] + virt_w[h];
    }
}

// ---------------------------------------------------------------------------
// Kernel 4: main. One CTA per (n, b); 8 warps; warp w owns m = w*16..w*16+15.
// Gather: lanes 0..23 own 4 heads each (1 byte/head). Per (b,n,m): 15x LDG.32
//   of fp8x4 from g_P8 (warp pulls one 96B row = 3 sectors), HADD2 half2
//   accumulate, scale by 1/(3*sp*P_SCALE), add bf16 spatial gather, store
//   bf16 to SMEM tile [m][h] (odd-word row stride -> conflict-free).
// Write: warp w owns h = w+8k, writes contiguous 129-wide output rows.
// ---------------------------------------------------------------------------
__global__ __launch_bounds__(256) void main_kernel(
    const float* __restrict__ attn_bias,
    const int*   __restrict__ spatial_pos,
    const int*   __restrict__ edge_input,
    const float* __restrict__ virt_w,
    float* __restrict__ out)
{
    __shared__ __nv_bfloat16 sval[128 * 98];  // 196B row stride, conflict-free
    __shared__ float s_ab[NP1];
    __shared__ float s_virt[NH];

    const int n    = blockIdx.x;
    const int b    = blockIdx.y;
    const int tid  = threadIdx.x;
    const int warp = tid >> 5;
    const int lane = tid & 31;

    if (tid < NH)  s_virt[tid] = virt_w[tid];
    if (tid < NP1) s_ab[tid] = attn_bias[(size_t)b * NSQ + (size_t)(n + 1) * NP1 + tid];

    // ---- gather phase ----
    if (lane < 24) {
        const int hoff = lane * 4;  // 4 heads per lane, 1 byte each in g_P8
#pragma unroll 1
        for (int mi = 0; mi < 16; ++mi) {
            const int m = warp * 16 + mi;
            const int* ip = edge_input + ((size_t)((b * 128 + n) * 128 + m)) * 15;
            __half2 acc01 = __half2half2(__ushort_as_half(0));
            __half2 acc23 = acc01;
#pragma unroll
            for (int r = 0; r < 15; ++r) {
                const int e = ip[r];                 // uniform across warp
                const int d = r / 3;                 // compile-time
                const uint32_t wv = *reinterpret_cast<const uint32_t*>(
                    g_P8 + ((size_t)d * NEDGE + e) * NH + hoff);
                const __half2 v01 = __half2(__nv_cvt_fp8x2_to_halfraw2(
                    (__nv_fp8x2_storage_t)(wv & 0xFFFFu), __NV_E4M3));
                const __half2 v23 = __half2(__nv_cvt_fp8x2_to_halfraw2(
                    (__nv_fp8x2_storage_t)(wv >> 16), __NV_E4M3));
                acc01 = __hadd2(acc01, v01);
                acc23 = __hadd2(acc23, v23);
            }
            const int s = spatial_pos[(size_t)(b * 128 + n) * 128 + m];
            int spn = (s <= 1) ? 1 : (s - 1);
            if (spn > 5) spn = 5;
            const float sc = c_scale[spn];

            // spatial bias gather (bf16 table, 4 heads = LDG.64)
            const uint2 spv = *reinterpret_cast<const uint2*>(
                g_SP + (size_t)s * NH + hoff);
            const float2 sp01 = __bfloat1622float2(
                *reinterpret_cast<const __nv_bfloat162*>(&spv.x));
            const float2 sp23 = __bfloat1622float2(
                *reinterpret_cast<const __nv_bfloat162*>(&spv.y));

            const float2 f01 = __half22float2(acc01);
            const float2 f23 = __half22float2(acc23);
            const float a0 = f01.x * sc + sp01.x;
            const float a1 = f01.y * sc + sp01.y;
            const float a2 = f23.x * sc + sp23.x;
            const float a3 = f23.y * sc + sp23.y;

            const __nv_bfloat162 o01 = __floats2bfloat162_rn(a0, a1);
            const __nv_bfloat162 o23 = __floats2bfloat162_rn(a2, a3);
            __nv_bfloat162* dst = reinterpret_cast<__nv_bfloat162*>(&sval[m * 98 + hoff]);
            dst[0] = o01;
            dst[1] = o23;
        }
    }
    __syncthreads();

    // ---- write phase: warp w handles h = w + 8*k ----
#pragma unroll 1
    for (int hk = 0; hk < 12; ++hk) {
        const int h = warp + 8 * hk;
        const float vw = s_virt[h];
        const size_t obase = ((((size_t)(h >> 3) * 16 + b) * 8) + (h & 7)) * NSQ
                             + (size_t)(n + 1) * NP1;
#pragma unroll
        for (int jj = 0; jj < 4; ++jj) {
            const int j = lane + 32 * jj;
            const float v = (j == 0) ? vw : __bfloat162float(sval[(j - 1) * 98 + h]);
            out[obase + j] = 2.f * s_ab[j] + v;
        }
        if (lane == 0)
            out[obase + 128] = 2.f * s_ab[128] + __bfloat162float(sval[127 * 98 + h]);
    }
}

// ---------------------------------------------------------------------------
// Launch. Input order: attn_bias f32, spatial_pos i32, node_attr f32 (unused),
// edge_input i32, edge_enc_w f32, edge_dis_w f32, spatial_enc_w f32, virt_w
// f32. Output f32 [12,16,8,129,129].
// ---------------------------------------------------------------------------
extern "C" void kernel_launch(void* const* d_in, const int* in_sizes, int n_in,
                              void* d_out, int out_size) {
    const float* attn_bias     = (const float*)d_in[0];
    const int*   spatial_pos   = (const int*)  d_in[1];
    const int*   edge_input    = (const int*)  d_in[3];
    const float* edge_enc_w    = (const float*)d_in[4];
    const float* edge_dis_w    = (const float*)d_in[5];
    const float* spatial_enc_w = (const float*)d_in[6];
    const float* virt_w        = (const float*)d_in[7];
    float* out = (float*)d_out;

    proj_kernel<<<dim3((NEDGE + 15) / 16, NDIST), NH>>>(edge_enc_w, edge_dis_w);
    cvt_spatial_kernel<<<(512 * NH + 255) / 256, 256>>>(spatial_enc_w);
    row0_kernel<<<16, 256>>>(attn_bias, virt_w, out);
    main_kernel<<<dim3(128, 16), 256>>>(attn_bias, spatial_pos, edge_input,
                                        virt_w, out);
}

// round 3
// speedup vs baseline: 1.4377x; 1.2579x over previous
#include <cuda_runtime.h>
#include <cuda_bf16.h>
#include <cuda_fp16.h>
#include <cuda_fp8.h>
#include <cstdint>

// Problem constants
#define NH    96          // heads total
#define NEDGE 1537        // edge table rows (incl. padding row 0)
#define NDIST 5           // MULTI_HOP
#define NP1   129         // N+1
#define NSQ   (129*129)
#define PROW  128         // padded fp8 row stride (bytes)

#define P_SCALE 64.0f     // fp8 table pre-scale (keeps 1/(3*sp*P_SCALE) fp16-normal)

// Projected edge table, fp8 e4m3, scaled by P_SCALE, row-padded to 128B
// (rows line-aligned; padding sectors never touched so no extra L2 traffic).
__device__ __align__(128) unsigned char g_P8[(size_t)NDIST * NEDGE * PROW];
// Spatial bias table in fp16: 512*96 entries.
__device__ __align__(16) __half g_SPh[512 * NH];

// hop normalizer with the fp8 scale folded in: 1/(3*sp*P_SCALE)
__constant__ float c_scale[6] = {0.f,
    1.f/(3.f*P_SCALE), 1.f/(6.f*P_SCALE), 1.f/(9.f*P_SCALE),
    1.f/(12.f*P_SCALE), 1.f/(15.f*P_SCALE)};

// ---------------------------------------------------------------------------
// Kernel 1: precompute projected table (24M MACs).
// ---------------------------------------------------------------------------
__global__ void proj_kernel(const float* __restrict__ enc,
                            const float* __restrict__ dis) {
    __shared__ float s_enc[16 * 32];
    const int d  = blockIdx.y;
    const int h  = threadIdx.x;          // 0..95
    const int e0 = blockIdx.x * 16;

    float w[32];
#pragma unroll
    for (int k = 0; k < 32; ++k)
        w[k] = dis[(d * 32 + k) * NH + h];   // coalesced over h

    for (int i = h; i < 16 * 32; i += 96) {
        const int e = e0 + (i >> 5);
        s_enc[i] = (e < NEDGE) ? enc[e * 32 + (i & 31)] : 0.f;
    }
    __syncthreads();

#pragma unroll 4
    for (int ei = 0; ei < 16; ++ei) {
        const int e = e0 + ei;
        if (e >= NEDGE) break;
        float acc = 0.f;
#pragma unroll
        for (int k = 0; k < 32; ++k)
            acc += s_enc[ei * 32 + k] * w[k];
        g_P8[((size_t)d * NEDGE + e) * PROW + h] =
            __nv_cvt_float_to_fp8(acc * P_SCALE, __NV_SATFINITE, __NV_E4M3);
    }
}

// ---------------------------------------------------------------------------
// Kernel 2: convert spatial_enc to fp16 table.
// ---------------------------------------------------------------------------
__global__ void cvt_spatial_kernel(const float* __restrict__ sp) {
    const int i = blockIdx.x * 256 + threadIdx.x;
    if (i < 512 * NH) g_SPh[i] = __float2half(sp[i]);
}

// ---------------------------------------------------------------------------
// Kernel 3: row 0 of the output (virtual token row).
// ---------------------------------------------------------------------------
__global__ void row0_kernel(const float* __restrict__ attn_bias,
                            const float* __restrict__ virt_w,
                            float* __restrict__ out) {
    const int b = blockIdx.x;
    for (int idx = threadIdx.x; idx < NH * NP1; idx += blockDim.x) {
        const int h = idx / NP1;
        const int j = idx - h * NP1;
        const size_t o = ((((size_t)(h >> 3) * 16 + b) * 8) + (h & 7)) * NSQ + j;
        out[o] = 2.f * attn_bias[(size_t)b * NSQ + j] + virt_w[h];
    }
}

// fp8x2 pair -> half2 accumulate (low 16 bits / high 16 bits of a word)
__device__ __forceinline__ void acc_word(__half2& lo, __half2& hi, uint32_t w) {
    lo = __hadd2(lo, __half2(__nv_cvt_fp8x2_to_halfraw2(
             (__nv_fp8x2_storage_t)(unsigned short)w, __NV_E4M3)));
    hi = __hadd2(hi, __half2(__nv_cvt_fp8x2_to_halfraw2(
             (__nv_fp8x2_storage_t)(w >> 16), __NV_E4M3)));
}

// ---------------------------------------------------------------------------
// Kernel 4: main. One CTA per (n, b); 8 warps; warp w owns m = w*16..w*16+15.
// Gather: (m, head-chunk) flattened to 96 slots = 3 full-warp iterations;
//   each slot = 16 heads via one LDG.128/row from the padded fp8 table.
//   half2 accumulate, fp16 HFMA2 epilogue (hop scale + spatial bias),
//   store half to SMEM tile [m][h] (stride 98 -> conflict-free column reads).
// Write: warp w owns h = w+8k, writes contiguous 129-wide output rows.
// ---------------------------------------------------------------------------
__global__ __launch_bounds__(256) void main_kernel(
    const float* __restrict__ attn_bias,
    const int*   __restrict__ spatial_pos,
    const int*   __restrict__ edge_input,
    const float* __restrict__ virt_w,
    float* __restrict__ out)
{
    __shared__ __half sval[128 * 98];   // 196B row stride, conflict-free cols
    __shared__ int    s_idx[128 * 15];  // this CTA's edge indices
    __shared__ int    s_sp[128];
    __shared__ float  s_ab[NP1];
    __shared__ float  s_virt[NH];

    const int n    = blockIdx.x;
    const int b    = blockIdx.y;
    const int tid  = threadIdx.x;
    const int warp = tid >> 5;
    const int lane = tid & 31;
    const size_t bn = (size_t)(b * 128 + n) * 128;

    // stage indices: 1920 ints = 480 int4 (block is 16B aligned & contiguous)
    {
        const int4* gs = reinterpret_cast<const int4*>(edge_input + bn * 15);
        int4* ds = reinterpret_cast<int4*>(s_idx);
        ds[tid] = gs[tid];
        if (tid < 224) ds[256 + tid] = gs[256 + tid];
    }
    if (tid < 128) s_sp[tid] = spatial_pos[bn + tid];
    if (tid < NH)  s_virt[tid] = virt_w[tid];
    if (tid < NP1) s_ab[tid] = attn_bias[(size_t)b * NSQ + (size_t)(n + 1) * NP1 + tid];
    __syncthreads();

    // ---- gather phase: 3 iterations x 32 lanes = 96 slots = 16 m x 6 chunks
    const __half2 hz = __float2half2_rn(0.f);
#pragma unroll
    for (int it = 0; it < 3; ++it) {
        const int slot  = it * 32 + lane;      // 0..95
        const int ml    = slot / 6;            // 0..15
        const int chunk = slot - ml * 6;       // 0..5
        const int m     = warp * 16 + ml;
        const unsigned char* pb = g_P8 + chunk * 16;
        const int* ip = s_idx + m * 15;

        __half2 a0 = hz, a1 = hz, a2 = hz, a3 = hz;
        __half2 a4 = hz, a5 = hz, a6 = hz, a7 = hz;
#pragma unroll
        for (int r = 0; r < 15; ++r) {
            const int e = ip[r];               // LDS
            const int d = r / 3;               // compile-time
            const uint4 v = *reinterpret_cast<const uint4*>(
                pb + (size_t)d * (NEDGE * PROW) + (size_t)e * PROW);
            acc_word(a0, a1, v.x);
            acc_word(a2, a3, v.y);
            acc_word(a4, a5, v.z);
            acc_word(a6, a7, v.w);
        }

        const int s = s_sp[m];
        int spn = (s <= 1) ? 1 : (s - 1);
        if (spn > 5) spn = 5;
        const __half2 sc2 = __float2half2_rn(c_scale[spn]);

        // spatial bias, 16 heads = 32B = 2x LDG.128
        const uint4* spv = reinterpret_cast<const uint4*>(
            g_SPh + (size_t)s * NH + chunk * 16);
        const uint4 sA = spv[0];
        const uint4 sB = spv[1];
        const __half2* sh = reinterpret_cast<const __half2*>(&sA);
        const __half2* sh2 = reinterpret_cast<const __half2*>(&sB);

        __half2* dst = reinterpret_cast<__half2*>(&sval[m * 98 + chunk * 16]);
        dst[0] = __hfma2(a0, sc2, sh[0]);
        dst[1] = __hfma2(a1, sc2, sh[1]);
        dst[2] = __hfma2(a2, sc2, sh[2]);
        dst[3] = __hfma2(a3, sc2, sh[3]);
        dst[4] = __hfma2(a4, sc2, sh2[0]);
        dst[5] = __hfma2(a5, sc2, sh2[1]);
        dst[6] = __hfma2(a6, sc2, sh2[2]);
        dst[7] = __hfma2(a7, sc2, sh2[3]);
    }
    __syncthreads();

    // ---- write phase: warp w handles h = w + 8*k ----
#pragma unroll 1
    for (int hk = 0; hk < 12; ++hk) {
        const int h = warp + 8 * hk;
        const float vw = s_virt[h];
        const size_t obase = ((((size_t)(h >> 3) * 16 + b) * 8) + (h & 7)) * NSQ
                             + (size_t)(n + 1) * NP1;
#pragma unroll
        for (int jj = 0; jj < 4; ++jj) {
            const int j = lane + 32 * jj;
            const float v = (j == 0) ? vw : __half2float(sval[(j - 1) * 98 + h]);
            out[obase + j] = 2.f * s_ab[j] + v;
        }
        if (lane == 0)
            out[obase + 128] = 2.f * s_ab[128] + __half2float(sval[127 * 98 + h]);
    }
}

// ---------------------------------------------------------------------------
// Launch. Input order: attn_bias f32, spatial_pos i32, node_attr f32 (unused),
// edge_input i32, edge_enc_w f32, edge_dis_w f32, spatial_enc_w f32, virt_w
// f32. Output f32 [12,16,8,129,129].
// ---------------------------------------------------------------------------
extern "C" void kernel_launch(void* const* d_in, const int* in_sizes, int n_in,
                              void* d_out, int out_size) {
    const float* attn_bias     = (const float*)d_in[0];
    const int*   spatial_pos   = (const int*)  d_in[1];
    const int*   edge_input    = (const int*)  d_in[3];
    const float* edge_enc_w    = (const float*)d_in[4];
    const float* edge_dis_w    = (const float*)d_in[5];
    const float* spatial_enc_w = (const float*)d_in[6];
    const float* virt_w        = (const float*)d_in[7];
    float* out = (float*)d_out;

    proj_kernel<<<dim3((NEDGE + 15) / 16, NDIST), NH>>>(edge_enc_w, edge_dis_w);
    cvt_spatial_kernel<<<(512 * NH + 255) / 256, 256>>>(spatial_enc_w);
    row0_kernel<<<16, 256>>>(attn_bias, virt_w, out);
    main_kernel<<<dim3(128, 16), 256>>>(attn_bias, spatial_pos, edge_input,
                                        virt_w, out);
}

// round 4
// speedup vs baseline: 1.4655x; 1.0193x over previous
#include <cuda_runtime.h>
#include <cuda_bf16.h>
#include <cuda_fp16.h>
#include <cuda_fp8.h>
#include <cstdint>

// Problem constants
#define NH    96          // heads total
#define NEDGE 1537        // edge table rows (incl. padding row 0)
#define NDIST 5           // MULTI_HOP
#define NP1   129         // N+1
#define NSQ   (129*129)
#define PROW  128         // padded fp8 row stride (bytes)
#define DSTRIDE (NEDGE * PROW)   // 196736 bytes per distance table (fits int32)

#define P_SCALE 64.0f     // fp8 table pre-scale (keeps 1/(3*sp*P_SCALE) fp16-normal)

// Projected edge table, fp8 e4m3, scaled by P_SCALE, row-padded to 128B.
__device__ __align__(128) unsigned char g_P8[(size_t)NDIST * DSTRIDE];
// Spatial bias table in fp16: 512*96 entries.
__device__ __align__(16) __half g_SPh[512 * NH];

// hop normalizer with the fp8 scale folded in: 1/(3*sp*P_SCALE)
__constant__ float c_scale[6] = {0.f,
    1.f/(3.f*P_SCALE), 1.f/(6.f*P_SCALE), 1.f/(9.f*P_SCALE),
    1.f/(12.f*P_SCALE), 1.f/(15.f*P_SCALE)};

// ---------------------------------------------------------------------------
// Kernel 1 (merged prep): blocks 0..484 -> projected-table GEMM
// (d = bx/97, e0 = (bx%97)*16); blocks 485..500 -> spatial fp32->fp16 convert.
// ---------------------------------------------------------------------------
__global__ void prep_kernel(const float* __restrict__ enc,
                            const float* __restrict__ dis,
                            const float* __restrict__ sp) {
    const int bx = blockIdx.x;
    const int h  = threadIdx.x;          // 0..95

    if (bx < 485) {
        __shared__ float s_enc[16 * 32];
        const int d  = bx / 97;
        const int e0 = (bx - d * 97) * 16;

        float w[32];
#pragma unroll
        for (int k = 0; k < 32; ++k)
            w[k] = dis[(d * 32 + k) * NH + h];   // coalesced over h

        for (int i = h; i < 16 * 32; i += 96) {
            const int e = e0 + (i >> 5);
            s_enc[i] = (e < NEDGE) ? enc[e * 32 + (i & 31)] : 0.f;
        }
        __syncthreads();

#pragma unroll 4
        for (int ei = 0; ei < 16; ++ei) {
            const int e = e0 + ei;
            if (e >= NEDGE) break;
            float acc = 0.f;
#pragma unroll
            for (int k = 0; k < 32; ++k)
                acc += s_enc[ei * 32 + k] * w[k];
            g_P8[(size_t)d * DSTRIDE + e * PROW + h] =
                __nv_cvt_float_to_fp8(acc * P_SCALE, __NV_SATFINITE, __NV_E4M3);
        }
    } else {
        // spatial convert: 512*96 = 49152 elems over 16 blocks x 96 threads
        const int t0 = ((bx - 485) * 96 + h) * 32;
#pragma unroll 8
        for (int k = 0; k < 32; ++k)
            g_SPh[t0 + k] = __float2half(sp[t0 + k]);
    }
}

// fp8x2 pair -> half2 accumulate (low 16 bits / high 16 bits of a word)
__device__ __forceinline__ void acc_word(__half2& lo, __half2& hi, uint32_t w) {
    lo = __hadd2(lo, __half2(__nv_cvt_fp8x2_to_halfraw2(
             (__nv_fp8x2_storage_t)(unsigned short)w, __NV_E4M3)));
    hi = __hadd2(hi, __half2(__nv_cvt_fp8x2_to_halfraw2(
             (__nv_fp8x2_storage_t)(w >> 16), __NV_E4M3)));
}

// ---------------------------------------------------------------------------
// Kernel 2: main. grid (129, 16). n==128 handles the virtual-token row 0.
// Otherwise one CTA per (n, b); 8 warps; warp w owns m = w*16..w*16+15.
// Gather: (m, head-chunk) flattened to 96 slots = 3 full-warp iterations;
//   each slot = 16 heads via LDG.128 rows from the padded fp8 table, in 5
//   batches of 3 (bounded live regs), half2 accumulate, fp16 HFMA2 epilogue.
// Write: warp w owns h = w+8k, writes contiguous 129-wide output rows.
// ---------------------------------------------------------------------------
__global__ __launch_bounds__(256, 5) void main_kernel(
    const float* __restrict__ attn_bias,
    const int*   __restrict__ spatial_pos,
    const int*   __restrict__ edge_input,
    const float* __restrict__ virt_w,
    float* __restrict__ out)
{
    const int n    = blockIdx.x;
    const int b    = blockIdx.y;
    const int tid  = threadIdx.x;

    if (n == 128) {
        // virtual-token row: out[l,b,a,0,j] = 2*ab[b,0,j] + virt[h]
        for (int idx = tid; idx < NH * NP1; idx += 256) {
            const int h = idx / NP1;
            const int j = idx - h * NP1;
            const size_t o = ((((size_t)(h >> 3) * 16 + b) * 8) + (h & 7)) * NSQ + j;
            out[o] = 2.f * attn_bias[(size_t)b * NSQ + j] + virt_w[h];
        }
        return;
    }

    __shared__ __half sval[128 * 98];   // 196B row stride, conflict-free cols
    __shared__ int    s_idx[128 * 15];  // this CTA's edge indices
    __shared__ int    s_sp[128];
    __shared__ float  s_ab[NP1];
    __shared__ float  s_virt[NH];

    const int warp = tid >> 5;
    const int lane = tid & 31;
    const size_t bn = (size_t)(b * 128 + n) * 128;

    // stage indices: 1920 ints = 480 int4
    {
        const int4* gs = reinterpret_cast<const int4*>(edge_input + bn * 15);
        int4* ds = reinterpret_cast<int4*>(s_idx);
        ds[tid] = gs[tid];
        if (tid < 224) ds[256 + tid] = gs[256 + tid];
    }
    if (tid < 128) s_sp[tid] = spatial_pos[bn + tid];
    if (tid < NH)  s_virt[tid] = virt_w[tid];
    if (tid < NP1) s_ab[tid] = attn_bias[(size_t)b * NSQ + (size_t)(n + 1) * NP1 + tid];
    __syncthreads();

    // ---- gather phase: 3 iterations x 32 lanes = 96 slots = 16 m x 6 chunks
    const __half2 hz = __float2half2_rn(0.f);
#pragma unroll
    for (int it = 0; it < 3; ++it) {
        const int slot  = it * 32 + lane;      // 0..95
        const int ml    = slot / 6;            // 0..15
        const int chunk = slot - ml * 6;       // 0..5
        const int m     = warp * 16 + ml;
        const unsigned char* pb = g_P8 + chunk * 16;
        const int* ip = s_idx + m * 15;

        __half2 a0 = hz, a1 = hz, a2 = hz, a3 = hz;
        __half2 a4 = hz, a5 = hz, a6 = hz, a7 = hz;
#pragma unroll
        for (int d = 0; d < 5; ++d) {
            // batch of 3 loads (bounded live registers, MLP=3)
            const unsigned e0 = (unsigned)ip[d * 3 + 0] * PROW + (unsigned)(d * DSTRIDE);
            const unsigned e1 = (unsigned)ip[d * 3 + 1] * PROW + (unsigned)(d * DSTRIDE);
            const unsigned e2 = (unsigned)ip[d * 3 + 2] * PROW + (unsigned)(d * DSTRIDE);
            const uint4 v0 = *reinterpret_cast<const uint4*>(pb + e0);
            const uint4 v1 = *reinterpret_cast<const uint4*>(pb + e1);
            const uint4 v2 = *reinterpret_cast<const uint4*>(pb + e2);
            acc_word(a0, a1, v0.x); acc_word(a2, a3, v0.y);
            acc_word(a4, a5, v0.z); acc_word(a6, a7, v0.w);
            acc_word(a0, a1, v1.x); acc_word(a2, a3, v1.y);
            acc_word(a4, a5, v1.z); acc_word(a6, a7, v1.w);
            acc_word(a0, a1, v2.x); acc_word(a2, a3, v2.y);
            acc_word(a4, a5, v2.z); acc_word(a6, a7, v2.w);
        }

        const int s = s_sp[m];
        int spn = (s <= 1) ? 1 : (s - 1);
        if (spn > 5) spn = 5;
        const __half2 sc2 = __float2half2_rn(c_scale[spn]);

        // spatial bias, 16 heads = 32B = 2x LDG.128
        const uint4* spv = reinterpret_cast<const uint4*>(
            g_SPh + s * NH + chunk * 16);
        const uint4 sA = spv[0];
        const uint4 sB = spv[1];
        const __half2* sh  = reinterpret_cast<const __half2*>(&sA);
        const __half2* sh2 = reinterpret_cast<const __half2*>(&sB);

        __half2* dst = reinterpret_cast<__half2*>(&sval[m * 98 + chunk * 16]);
        dst[0] = __hfma2(a0, sc2, sh[0]);
        dst[1] = __hfma2(a1, sc2, sh[1]);
        dst[2] = __hfma2(a2, sc2, sh[2]);
        dst[3] = __hfma2(a3, sc2, sh[3]);
        dst[4] = __hfma2(a4, sc2, sh2[0]);
        dst[5] = __hfma2(a5, sc2, sh2[1]);
        dst[6] = __hfma2(a6, sc2, sh2[2]);
        dst[7] = __hfma2(a7, sc2, sh2[3]);
    }
    __syncthreads();

    // ---- write phase: warp w handles h = w + 8*hk; obase linear in hk ----
    size_t obase = ((size_t)b * 8 + warp) * NSQ + (size_t)(n + 1) * NP1;
    const __half* scol = sval + warp;       // + 8*hk each step (h = warp+8hk)
#pragma unroll 1
    for (int hk = 0; hk < 12; ++hk) {
        const int h = warp + 8 * hk;
        const float vw = s_virt[h];
        const __half* sc = scol + 8 * hk;
#pragma unroll
        for (int jj = 0; jj < 4; ++jj) {
            const int j = lane + 32 * jj;
            const float v = (j == 0) ? vw : __half2float(sc[(j - 1) * 98]);
            out[obase + j] = 2.f * s_ab[j] + v;
        }
        if (lane == 0)
            out[obase + 128] = 2.f * s_ab[128] + __half2float(sc[127 * 98]);
        obase += (size_t)128 * NSQ;         // next hk: h += 8 -> +16*8*NSQ/... = 128*NSQ
    }
}

// ---------------------------------------------------------------------------
// Launch. Input order: attn_bias f32, spatial_pos i32, node_attr f32 (unused),
// edge_input i32, edge_enc_w f32, edge_dis_w f32, spatial_enc_w f32, virt_w
// f32. Output f32 [12,16,8,129,129].
// ---------------------------------------------------------------------------
extern "C" void kernel_launch(void* const* d_in, const int* in_sizes, int n_in,
                              void* d_out, int out_size) {
    const float* attn_bias     = (const float*)d_in[0];
    const int*   spatial_pos   = (const int*)  d_in[1];
    const int*   edge_input    = (const int*)  d_in[3];
    const float* edge_enc_w    = (const float*)d_in[4];
    const float* edge_dis_w    = (const float*)d_in[5];
    const float* spatial_enc_w = (const float*)d_in[6];
    const float* virt_w        = (const float*)d_in[7];
    float* out = (float*)d_out;

    prep_kernel<<<501, NH>>>(edge_enc_w, edge_dis_w, spatial_enc_w);
    main_kernel<<<dim3(129, 16), 256>>>(attn_bias, spatial_pos, edge_input,
                                        virt_w, out);
}

// round 5
// speedup vs baseline: 1.5786x; 1.0772x over previous
#include <cuda_runtime.h>
#include <cuda_bf16.h>
#include <cuda_fp16.h>
#include <cuda_fp8.h>
#include <cstdint>

// Problem constants
#define NH    96          // heads total
#define NEDGE 1537        // edge table rows (incl. padding row 0)
#define NDIST 5           // MULTI_HOP
#define NP1   129         // N+1
#define NSQ   (129*129)
#define PROW  128         // padded fp8 row stride (bytes)
#define DSTRIDE (NEDGE * PROW)   // bytes per distance table (fits int32)

#define P_SCALE 64.0f     // fp8 table pre-scale

// Projected edge table, fp8 e4m3, scaled by P_SCALE, row-padded to 128B.
__device__ __align__(128) unsigned char g_P8[(size_t)NDIST * DSTRIDE];
// Spatial bias table in fp16: 512*96 entries.
__device__ __align__(16) __half g_SPh[512 * NH];

// hop normalizer with the fp8 scale folded in: 1/(3*sp*P_SCALE)
__constant__ float c_scale[6] = {0.f,
    1.f/(3.f*P_SCALE), 1.f/(6.f*P_SCALE), 1.f/(9.f*P_SCALE),
    1.f/(12.f*P_SCALE), 1.f/(15.f*P_SCALE)};

// per-r table base offsets (d = r/3)
__constant__ unsigned c_doff[15] = {
    0, 0, 0,
    1u*DSTRIDE, 1u*DSTRIDE, 1u*DSTRIDE,
    2u*DSTRIDE, 2u*DSTRIDE, 2u*DSTRIDE,
    3u*DSTRIDE, 3u*DSTRIDE, 3u*DSTRIDE,
    4u*DSTRIDE, 4u*DSTRIDE, 4u*DSTRIDE};

// ---------------------------------------------------------------------------
// Kernel 1 (merged prep): blocks 0..484 -> projected-table GEMM;
// blocks 485..500 -> spatial fp32->fp16 convert.
// ---------------------------------------------------------------------------
__global__ void prep_kernel(const float* __restrict__ enc,
                            const float* __restrict__ dis,
                            const float* __restrict__ sp) {
    const int bx = blockIdx.x;
    const int h  = threadIdx.x;          // 0..95

    if (bx < 485) {
        __shared__ float s_enc[16 * 32];
        const int d  = bx / 97;
        const int e0 = (bx - d * 97) * 16;

        float w[32];
#pragma unroll
        for (int k = 0; k < 32; ++k)
            w[k] = dis[(d * 32 + k) * NH + h];

        for (int i = h; i < 16 * 32; i += 96) {
            const int e = e0 + (i >> 5);
            s_enc[i] = (e < NEDGE) ? enc[e * 32 + (i & 31)] : 0.f;
        }
        __syncthreads();

#pragma unroll 4
        for (int ei = 0; ei < 16; ++ei) {
            const int e = e0 + ei;
            if (e >= NEDGE) break;
            float acc = 0.f;
#pragma unroll
            for (int k = 0; k < 32; ++k)
                acc += s_enc[ei * 32 + k] * w[k];
            g_P8[(size_t)d * DSTRIDE + e * PROW + h] =
                __nv_cvt_float_to_fp8(acc * P_SCALE, __NV_SATFINITE, __NV_E4M3);
        }
    } else {
        const int t0 = ((bx - 485) * 96 + h) * 32;
#pragma unroll 8
        for (int k = 0; k < 32; ++k)
            g_SPh[t0 + k] = __float2half(sp[t0 + k]);
    }
}

// fp8x2 pair -> half2 accumulate (low / high 16 bits of a word)
__device__ __forceinline__ void acc_word(__half2& lo, __half2& hi, uint32_t w) {
    lo = __hadd2(lo, __half2(__nv_cvt_fp8x2_to_halfraw2(
             (__nv_fp8x2_storage_t)(unsigned short)w, __NV_E4M3)));
    hi = __hadd2(hi, __half2(__nv_cvt_fp8x2_to_halfraw2(
             (__nv_fp8x2_storage_t)(w >> 16), __NV_E4M3)));
}

// ---------------------------------------------------------------------------
// Kernel 2: main. grid (129, 16); n==128 is the virtual-token row.
// Gather: (m, head-chunk) flattened to 96 slots = 3 full-warp iterations;
//   each slot = 16 heads; the 15 row-gathers issue as two hoisted batches
//   (8 + 7 LDG.128 in flight) to keep MLP high without register spills.
// Write: warp w owns h = w+8k, contiguous 129-wide output rows.
// ---------------------------------------------------------------------------
__global__ __launch_bounds__(256, 4) void main_kernel(
    const float* __restrict__ attn_bias,
    const int*   __restrict__ spatial_pos,
    const int*   __restrict__ edge_input,
    const float* __restrict__ virt_w,
    float* __restrict__ out)
{
    const int n    = blockIdx.x;
    const int b    = blockIdx.y;
    const int tid  = threadIdx.x;

    if (n == 128) {
        for (int idx = tid; idx < NH * NP1; idx += 256) {
            const int h = idx / NP1;
            const int j = idx - h * NP1;
            const size_t o = ((((size_t)(h >> 3) * 16 + b) * 8) + (h & 7)) * NSQ + j;
            out[o] = 2.f * attn_bias[(size_t)b * NSQ + j] + virt_w[h];
        }
        return;
    }

    __shared__ __half sval[128 * 98];   // 196B row stride, conflict-free cols
    __shared__ int    s_idx[128 * 15];
    __shared__ int    s_sp[128];
    __shared__ float  s_ab[NP1];
    __shared__ float  s_virt[NH];

    const int warp = tid >> 5;
    const int lane = tid & 31;
    const size_t bn = (size_t)(b * 128 + n) * 128;

    // stage indices: 1920 ints = 480 int4
    {
        const int4* gs = reinterpret_cast<const int4*>(edge_input + bn * 15);
        int4* ds = reinterpret_cast<int4*>(s_idx);
        ds[tid] = gs[tid];
        if (tid < 224) ds[256 + tid] = gs[256 + tid];
    }
    if (tid < 128) s_sp[tid] = spatial_pos[bn + tid];
    if (tid < NH)  s_virt[tid] = virt_w[tid];
    if (tid < NP1) s_ab[tid] = attn_bias[(size_t)b * NSQ + (size_t)(n + 1) * NP1 + tid];
    __syncthreads();

    // ---- gather phase: 3 iterations x 32 lanes = 96 slots = 16 m x 6 chunks
    const __half2 hz = __float2half2_rn(0.f);
#pragma unroll
    for (int it = 0; it < 3; ++it) {
        const int slot  = it * 32 + lane;      // 0..95
        const int ml    = slot / 6;            // 0..15
        const int chunk = slot - ml * 6;       // 0..5
        const int m     = warp * 16 + ml;
        const unsigned char* pb = g_P8 + chunk * 16;
        const int* ip = s_idx + m * 15;

        __half2 a0 = hz, a1 = hz, a2 = hz, a3 = hz;
        __half2 a4 = hz, a5 = hz, a6 = hz, a7 = hz;

        // batch 1: 8 loads in flight
        uint4 v[8];
#pragma unroll
        for (int r = 0; r < 8; ++r)
            v[r] = *reinterpret_cast<const uint4*>(
                pb + ((unsigned)ip[r] * PROW + c_doff[r]));
#pragma unroll
        for (int r = 0; r < 8; ++r) {
            acc_word(a0, a1, v[r].x); acc_word(a2, a3, v[r].y);
            acc_word(a4, a5, v[r].z); acc_word(a6, a7, v[r].w);
        }
        // batch 2: 7 loads in flight (overlaps batch-1 accumulate retire)
        uint4 u[7];
#pragma unroll
        for (int r = 0; r < 7; ++r)
            u[r] = *reinterpret_cast<const uint4*>(
                pb + ((unsigned)ip[8 + r] * PROW + c_doff[8 + r]));
#pragma unroll
        for (int r = 0; r < 7; ++r) {
            acc_word(a0, a1, u[r].x); acc_word(a2, a3, u[r].y);
            acc_word(a4, a5, u[r].z); acc_word(a6, a7, u[r].w);
        }

        const int s = s_sp[m];
        int spn = (s <= 1) ? 1 : (s - 1);
        if (spn > 5) spn = 5;
        const __half2 sc2 = __float2half2_rn(c_scale[spn]);

        const uint4* spv = reinterpret_cast<const uint4*>(
            g_SPh + s * NH + chunk * 16);
        const uint4 sA = spv[0];
        const uint4 sB = spv[1];
        const __half2* sh  = reinterpret_cast<const __half2*>(&sA);
        const __half2* sh2 = reinterpret_cast<const __half2*>(&sB);

        __half2* dst = reinterpret_cast<__half2*>(&sval[m * 98 + chunk * 16]);
        dst[0] = __hfma2(a0, sc2, sh[0]);
        dst[1] = __hfma2(a1, sc2, sh[1]);
        dst[2] = __hfma2(a2, sc2, sh[2]);
        dst[3] = __hfma2(a3, sc2, sh[3]);
        dst[4] = __hfma2(a4, sc2, sh2[0]);
        dst[5] = __hfma2(a5, sc2, sh2[1]);
        dst[6] = __hfma2(a6, sc2, sh2[2]);
        dst[7] = __hfma2(a7, sc2, sh2[3]);
    }
    __syncthreads();

    // ---- write phase: warp w handles h = w + 8*hk; obase linear in hk ----
    size_t obase = ((size_t)b * 8 + warp) * NSQ + (size_t)(n + 1) * NP1;
    const __half* scol = sval + warp;
#pragma unroll 1
    for (int hk = 0; hk < 12; ++hk) {
        const int h = warp + 8 * hk;
        const float vw = s_virt[h];
        const __half* sc = scol + 8 * hk;
#pragma unroll
        for (int jj = 0; jj < 4; ++jj) {
            const int j = lane + 32 * jj;
            const float v = (j == 0) ? vw : __half2float(sc[(j - 1) * 98]);
            out[obase + j] = 2.f * s_ab[j] + v;
        }
        if (lane == 0)
            out[obase + 128] = 2.f * s_ab[128] + __half2float(sc[127 * 98]);
        obase += (size_t)128 * NSQ;
    }
}

// ---------------------------------------------------------------------------
// Launch. Input order: attn_bias f32, spatial_pos i32, node_attr f32 (unused),
// edge_input i32, edge_enc_w f32, edge_dis_w f32, spatial_enc_w f32, virt_w
// f32. Output f32 [12,16,8,129,129].
// ---------------------------------------------------------------------------
extern "C" void kernel_launch(void* const* d_in, const int* in_sizes, int n_in,
                              void* d_out, int out_size) {
    const float* attn_bias     = (const float*)d_in[0];
    const int*   spatial_pos   = (const int*)  d_in[1];
    const int*   edge_input    = (const int*)  d_in[3];
    const float* edge_enc_w    = (const float*)d_in[4];
    const float* edge_dis_w    = (const float*)d_in[5];
    const float* spatial_enc_w = (const float*)d_in[6];
    const float* virt_w        = (const float*)d_in[7];
    float* out = (float*)d_out;

    prep_kernel<<<501, NH>>>(edge_enc_w, edge_dis_w, spatial_enc_w);
    main_kernel<<<dim3(129, 16), 256>>>(attn_bias, spatial_pos, edge_input,
                                        virt_w, out);
}